// round 7
// baseline (speedup 1.0000x reference)
#include <cuda_runtime.h>
#include <cuda_bf16.h>
#include <cstdint>

#define BB 4
#define HH 256
#define CC 80
#define TX 256
#define TY 1024
#define NEGV (-1e9f)

// Output layout (float32):
#define OFF_OEN  0
#define OFF_LOGP 1048576
#define OFF_ATTN 2097152
#define OFF_DR   3145728

// -------- device scratch --------
__device__ float g_A  [BB*CC*TX];
__device__ float g_Bc [BB*CC*TX];
__device__ float g_cst[BB*TX];
__device__ float g_lpT[BB*TY*TX];   // masked logp, transposed [b][y][x]
__device__ int   g_idx[BB*TY];      // alignment index per y (-1 = inactive)

__device__ __forceinline__ void cp_async16(void* smem_dst, const void* gmem_src) {
    unsigned sa = (unsigned)__cvta_generic_to_shared(smem_dst);
    asm volatile("cp.async.cg.shared.global [%0], [%1], 16;\n"
                 :: "r"(sa), "l"(gmem_src));
}

// =====================================================================
// K0: slot-shift no-op so ncu's captured slot (4th launch) lands on k_dp
// =====================================================================
__global__ void k_slot() {}

// =====================================================================
// K1: per-(b,x) channel precompute
// =====================================================================
__global__ void k_pre(const float* __restrict__ mu,
                      const float* __restrict__ ls) {
    int b = blockIdx.x;
    int x = threadIdx.x;
    float s3 = 0.f, sl = 0.f;
    #pragma unroll 4
    for (int c = 0; c < CC; c++) {
        int o = (b * CC + c) * TX + x;
        float l = ls[o];
        float m = mu[o];
        float w = expf(-2.0f * l);
        g_A [o] = (-0.5f / (float)CC) * w;
        g_Bc[o] = (1.0f / (float)CC) * w * m;
        s3 += w * m * m;
        sl += l;
    }
    g_cst[b * TX + x] = (-0.5f / (float)CC) * (s3 + sl);
}

// =====================================================================
// K2: logp GEMM  logp[b,x,y] = sum_c A*y^2 + B*y + cst
// =====================================================================
#define TSX 64
#define TSY 64
#define KCH 40

__global__ __launch_bounds__(256, 2)
void k_logp(const float* __restrict__ y,
            const int* __restrict__ xl,
            const int* __restrict__ yl,
            float* __restrict__ out) {
    __shared__ float sA [KCH][TSX];
    __shared__ float sB [KCH][TSX];
    __shared__ float sY [KCH][TSY];
    __shared__ float sY2[KCH][TSY];

    int b  = blockIdx.z;
    int x0 = blockIdx.y * TSX;
    int y0 = blockIdx.x * TSY;
    int tid = threadIdx.x;
    int ty = tid & 15;
    int tx = tid >> 4;
    int xr = tx * 4;
    int yc = ty * 4;

    float acc[4][4] = {};

    for (int kc = 0; kc < CC; kc += KCH) {
        __syncthreads();
        #pragma unroll
        for (int i = tid; i < KCH * TSX; i += 256) {
            int c = i >> 6, j = i & 63;
            int oa = (b * CC + (kc + c)) * TX + x0 + j;
            sA[c][j] = g_A[oa];
            sB[c][j] = g_Bc[oa];
            float yv = y[(b * CC + (kc + c)) * TY + y0 + j];
            sY [c][j] = yv;
            sY2[c][j] = yv * yv;
        }
        __syncthreads();

        #pragma unroll 8
        for (int c = 0; c < KCH; c++) {
            float4 a  = *(const float4*)&sA [c][xr];
            float4 bb = *(const float4*)&sB [c][xr];
            float4 yv = *(const float4*)&sY [c][yc];
            float4 y2 = *(const float4*)&sY2[c][yc];
            float av[4] = {a.x, a.y, a.z, a.w};
            float bv[4] = {bb.x, bb.y, bb.z, bb.w};
            float yvv[4] = {yv.x, yv.y, yv.z, yv.w};
            float y2v[4] = {y2.x, y2.y, y2.z, y2.w};
            #pragma unroll
            for (int i = 0; i < 4; i++)
                #pragma unroll
                for (int j = 0; j < 4; j++) {
                    acc[i][j] = fmaf(av[i], y2v[j], acc[i][j]);
                    acc[i][j] = fmaf(bv[i], yvv[j], acc[i][j]);
                }
        }
    }

    float cst_i[4];
    #pragma unroll
    for (int i = 0; i < 4; i++)
        cst_i[i] = g_cst[b * TX + x0 + xr + i];

    int xlen = xl[b], ylen = yl[b];

    #pragma unroll
    for (int i = 0; i < 4; i++) {
        int gx = x0 + xr + i;
        float4 r;
        r.x = acc[i][0] + cst_i[i];
        r.y = acc[i][1] + cst_i[i];
        r.z = acc[i][2] + cst_i[i];
        r.w = acc[i][3] + cst_i[i];
        *(float4*)&out[OFF_LOGP + ((size_t)(b * TX + gx)) * TY + y0 + yc] = r;
    }

    #pragma unroll
    for (int j = 0; j < 4; j++) {
        int gy = y0 + yc + j;
        bool ym = gy < ylen;
        float4 t;
        t.x = (ym && (x0 + xr + 0) < xlen) ? acc[0][j] + cst_i[0] : NEGV;
        t.y = (ym && (x0 + xr + 1) < xlen) ? acc[1][j] + cst_i[1] : NEGV;
        t.z = (ym && (x0 + xr + 2) < xlen) ? acc[2][j] + cst_i[2] : NEGV;
        t.w = (ym && (x0 + xr + 3) < xlen) ? acc[3][j] + cst_i[3] : NEGV;
        *(float4*)&g_lpT[((size_t)(b * TY + gy)) * TX + x0 + xr] = t;
    }
}

// =====================================================================
// K3: Viterbi DP — 4 specialized warps, 2-step-fused consumer.
//   w0: recurrence, 2 rows per group, one 64-bit shfl per group
//   w1,w2: diag bits from vring, one chunk behind consumer
//   w3: cp.async producer, triple-buffered rows
// =====================================================================
#define DPC 32
// smem layout (bytes):
//   rows:  float4[3][32*64]  = 98304   @ 0
//   vring: float4[3][32*64]  = 98304   @ 98304
//   diag:  unsigned[32][256] = 32768   @ 196608
//   dr:    int[256]          = 1024    @ 229376
//   cum:   int[257]          = 1028    @ 230400
#define DP_SMEM_BYTES 231456

__global__ __launch_bounds__(128, 1)
void k_dp(const int* __restrict__ xl,
          const int* __restrict__ yl,
          float* __restrict__ out) {
    extern __shared__ char smem[];
    float4*   rows  = (float4*)smem;                      // [3][2048]
    float4*   vring = (float4*)(smem + 98304);            // [3][2048]
    unsigned* diag  = (unsigned*)(smem + 196608);         // [32][256]
    int*      s_dr  = (int*)(smem + 229376);
    int*      s_cum = (int*)(smem + 230400);

    int b    = blockIdx.x;
    int tid  = threadIdx.x;
    int wid  = tid >> 5;
    int lane = tid & 31;

    int xlen = xl[b], ylen = yl[b];
    int nck  = (ylen + DPC - 1) / DPC;     // 16..32 chunks of 32 steps

    const float4* lp4 = (const float4*)(g_lpT + (size_t)b * TY * TX);

    s_dr[tid] = 0; s_dr[tid + 128] = 0;

    if (wid == 0) {
        // seed "row -1" = v_init into vring buffer 2, row 31
        float4 z0 = make_float4(NEGV, NEGV, NEGV, NEGV);
        float4 z1 = z0;
        if (lane == 0) z0.x = 0.0f;
        vring[2 * 2048 + 31 * 64 + lane * 2]     = z0;
        vring[2 * 2048 + 31 * 64 + lane * 2 + 1] = z1;
    } else if (wid == 3) {
        // prologue: chunks 0 and 1 into rows[0], rows[1]
        for (int i = lane; i < 2048; i += 32) cp_async16(rows + i, lp4 + i);
        asm volatile("cp.async.commit_group;\n");
        for (int i = lane; i < 2048; i += 32)
            cp_async16(rows + 2048 + i, lp4 + 2048 + i);
        asm volatile("cp.async.commit_group;\n");
        asm volatile("cp.async.wait_group 1;\n" ::: "memory");  // chunk 0 done
    }
    __syncthreads();                                   // barrier #0

    if (wid == 0) {
        // ---------- consumer: 2 rows per group, 1 shfl64 per group ----------
        float v[8];
        #pragma unroll
        for (int i = 0; i < 8; i++) v[i] = NEGV;
        if (lane == 0) v[0] = 0.0f;

        float4 c0 = rows[lane * 2],      c1 = rows[lane * 2 + 1];
        float4 d0 = rows[64 + lane * 2], d1 = rows[64 + lane * 2 + 1];

        #pragma unroll 1
        for (int ck = 0; ck < nck; ck++) {
            const float4* rb = rows  + (ck % 3) * 2048;
            float4*       vr = vring + (ck % 3) * 2048;

            #pragma unroll
            for (int g = 0; g < 16; g++) {
                float4 e0, e1, f0, f1;
                if (g < 15) {
                    e0 = rb[(2 * g + 2) * 64 + lane * 2];
                    e1 = rb[(2 * g + 2) * 64 + lane * 2 + 1];
                    f0 = rb[(2 * g + 3) * 64 + lane * 2];
                    f1 = rb[(2 * g + 3) * 64 + lane * 2 + 1];
                }
                float cc[8] = {c0.x, c0.y, c0.z, c0.w,
                               c1.x, c1.y, c1.z, c1.w};
                float dd[8] = {d0.x, d0.y, d0.z, d0.w,
                               d1.x, d1.y, d1.z, d1.w};

                // u = v_{t+1}: compute u[7] first (local), shfl {v7,u7} early
                float u7 = cc[7] + fmaxf(v[7], v[6]);
                unsigned long long pk =
                    ((unsigned long long)__float_as_uint(u7) << 32) |
                    (unsigned long long)__float_as_uint(v[7]);
                unsigned long long pg = __shfl_up_sync(0xffffffffu, pk, 1);
                float pv7 = __uint_as_float((unsigned)(pg & 0xffffffffull));
                float pu7 = __uint_as_float((unsigned)(pg >> 32));
                if (lane == 0) { pv7 = NEGV; pu7 = NEGV; }

                float u[8], w[8];
                u[7] = u7;
                #pragma unroll
                for (int i = 6; i >= 1; i--)
                    u[i] = cc[i] + fmaxf(v[i], v[i - 1]);
                #pragma unroll
                for (int i = 7; i >= 2; i--)
                    w[i] = dd[i] + fmaxf(u[i], u[i - 1]);
                u[0] = cc[0] + fmaxf(v[0], pv7);
                w[1] = dd[1] + fmaxf(u[1], u[0]);
                w[0] = dd[0] + fmaxf(u[0], pu7);

                float4* p0 = vr + (2 * g) * 64;
                p0[lane * 2]     = make_float4(u[0], u[1], u[2], u[3]);
                p0[lane * 2 + 1] = make_float4(u[4], u[5], u[6], u[7]);
                float4* p1 = vr + (2 * g + 1) * 64;
                p1[lane * 2]     = make_float4(w[0], w[1], w[2], w[3]);
                p1[lane * 2 + 1] = make_float4(w[4], w[5], w[6], w[7]);

                #pragma unroll
                for (int i = 0; i < 8; i++) v[i] = w[i];
                if (g < 15) { c0 = e0; c1 = e1; d0 = f0; d1 = f1; }
            }
            __syncthreads();                           // barrier #ck+1
            if (ck + 1 < nck) {
                const float4* nb = rows + ((ck + 1) % 3) * 2048;
                c0 = nb[lane * 2];      c1 = nb[lane * 2 + 1];
                d0 = nb[64 + lane * 2]; d1 = nb[64 + lane * 2 + 1];
            }
        }
    } else if (wid < 3) {
        // ---------------- diag warps: bits from vring, 1 chunk behind ----
        int xq = (wid - 1) * 32 + lane;        // float4 index within a row
        bool l0 = (lane == 0);
        #pragma unroll 1
        for (int ck = 0; ck < nck; ck++) {
            __syncthreads();                           // barrier #ck+1
            const float4* vr    = vring + (ck % 3) * 2048;
            const float4* vprev = vring + ((ck + 2) % 3) * 2048;
            unsigned db0 = 0, db1 = 0, db2 = 0, db3 = 0;
            #pragma unroll
            for (int r = 0; r < 32; r++) {
                const float4* pr = (r == 0) ? (vprev + 31 * 64)
                                            : (vr + (r - 1) * 64);
                float4 V = pr[xq];
                float pm1 = __shfl_up_sync(0xffffffffu, V.w, 1);
                if (l0) pm1 = (wid == 1) ? NEGV : ((const float*)pr)[127];
                unsigned bit = 1u << r;
                if (pm1 > V.x) db0 |= bit;
                if (V.x > V.y) db1 |= bit;
                if (V.y > V.z) db2 |= bit;
                if (V.z > V.w) db3 |= bit;
            }
            *(uint4*)&diag[ck * 256 + xq * 4] = make_uint4(db0, db1, db2, db3);
        }
    } else {
        // ---------------- producer: chunk ck+2 each window ----------------
        #pragma unroll 1
        for (int ck = 0; ck < nck; ck++) {
            if (ck + 2 < nck) {
                const float4* src = lp4 + (ck + 2) * 2048;
                float4* dst = rows + ((ck + 2) % 3) * 2048;
                for (int i = lane; i < 2048; i += 32)
                    cp_async16(dst + i, src + i);
                asm volatile("cp.async.commit_group;\n");
                asm volatile("cp.async.wait_group 1;\n" ::: "memory");
            } else {
                asm volatile("cp.async.wait_group 0;\n" ::: "memory");
            }
            __syncthreads();                           // barrier #ck+1
        }
    }
    __syncthreads();   // final: diag warps finished last chunk

    // ---- backtrack: run-length over diag words (lane 0) ----
    if (tid == 0) {
        int idx = xlen - 1;
        int yy  = ylen - 1;
        while (yy >= 0) {
            if (idx == 0) { s_dr[0] += yy + 1; break; }
            int yw = yy >> 5;
            unsigned mask = ((yy & 31) == 31) ? 0xffffffffu
                                              : ((2u << (yy & 31)) - 1u);
            unsigned m = diag[yw * 256 + idx] & mask;
            if (m) {
                int ystar = (yw << 5) + (31 - __clz(m));
                s_dr[idx] += yy - ystar + 1;
                idx--;
                yy = ystar - 1;
            } else {
                s_dr[idx] += yy - (yw << 5) + 1;
                yy = (yw << 5) - 1;
            }
        }
    }
    __syncthreads();

    // ---- exclusive cumsum of durations (warp 0) ----
    if (wid == 0) {
        int t[8], run[8];
        int tot = 0;
        #pragma unroll
        for (int i = 0; i < 8; i++) {
            t[i] = s_dr[lane * 8 + i];
            tot += t[i];
            run[i] = tot;
        }
        int sc = tot;
        #pragma unroll
        for (int d = 1; d < 32; d <<= 1) {
            int n = __shfl_up_sync(0xffffffffu, sc, d);
            if (lane >= d) sc += n;
        }
        int excl = sc - tot;
        if (lane == 0) s_cum[0] = 0;
        #pragma unroll
        for (int i = 0; i < 8; i++)
            s_cum[lane * 8 + i + 1] = excl + run[i];

        #pragma unroll
        for (int i = 0; i < 8; i++)
            out[OFF_DR + b * TX + lane * 8 + i] = (float)t[i];
    }
    __syncthreads();

    // ---- g_idx via binary search (8 y per thread) ----
    #pragma unroll
    for (int k = 0; k < TY / 128; k++) {
        int yy = k * 128 + tid;
        int r = -1;
        if (yy < ylen) {
            int lo = 0, hi = TX - 1;
            #pragma unroll
            for (int s = 0; s < 8; s++) {
                int mid = (lo + hi) >> 1;
                if (yy >= s_cum[mid + 1]) lo = mid + 1; else hi = mid;
            }
            r = lo;
        }
        g_idx[b * TY + yy] = r;
    }
}

// =====================================================================
// K4: fused epilogue — 4 rows per block
// =====================================================================
__global__ __launch_bounds__(256)
void k_epi(const float* __restrict__ en, float* __restrict__ out) {
    __shared__ float se[4][TX];
    int bid = blockIdx.x;
    int tid = threadIdx.x;
    int row0 = bid * 4;

    if (row0 < BB * TX) {
        int b = row0 >> 8;
        int4 id = *(const int4*)&g_idx[b * TY + tid * 4];
        #pragma unroll
        for (int rr = 0; rr < 4; rr++) {
            int x = (row0 + rr) & 255;
            float4 r;
            r.x = (id.x == x) ? 1.0f : 0.0f;
            r.y = (id.y == x) ? 1.0f : 0.0f;
            r.z = (id.z == x) ? 1.0f : 0.0f;
            r.w = (id.w == x) ? 1.0f : 0.0f;
            *(float4*)&out[OFF_ATTN + (size_t)(row0 + rr) * TY + tid * 4] = r;
        }
    } else {
        int r0 = row0 - BB * TX;
        int b  = r0 >> 8;
        {
            int rr = tid >> 6;
            int h  = (r0 + rr) & 255;
            *(float4*)&se[rr][(tid & 63) * 4] =
                *(const float4*)&en[(b * HH + h) * TX + (tid & 63) * 4];
        }
        __syncthreads();
        int4 id = *(const int4*)&g_idx[b * TY + tid * 4];
        #pragma unroll
        for (int rr = 0; rr < 4; rr++) {
            float4 r;
            r.x = (id.x >= 0) ? se[rr][id.x] : 0.0f;
            r.y = (id.y >= 0) ? se[rr][id.y] : 0.0f;
            r.z = (id.z >= 0) ? se[rr][id.z] : 0.0f;
            r.w = (id.w >= 0) ? se[rr][id.w] : 0.0f;
            *(float4*)&out[OFF_OEN + (size_t)(r0 + rr) * TY + tid * 4] = r;
        }
    }
}

// =====================================================================
extern "C" void kernel_launch(void* const* d_in, const int* in_sizes, int n_in,
                              void* d_out, int out_size) {
    const float* en = (const float*)d_in[0];
    const float* mu = (const float*)d_in[1];
    const float* ls = (const float*)d_in[2];
    const float* y  = (const float*)d_in[3];
    const int*   xl = (const int*)d_in[4];
    const int*   yl = (const int*)d_in[5];
    float* out = (float*)d_out;

    cudaFuncSetAttribute(k_dp, cudaFuncAttributeMaxDynamicSharedMemorySize,
                         DP_SMEM_BYTES);

    k_pre<<<BB, TX>>>(mu, ls);

    dim3 g2(TY / TSY, TX / TSX, BB);   // (16, 4, 4)
    k_logp<<<g2, 256>>>(y, xl, yl, out);

    k_slot<<<1, 32>>>();               // shift ncu capture slot onto k_dp

    k_dp<<<BB, 128, DP_SMEM_BYTES>>>(xl, yl, out);

    k_epi<<<2 * BB * TX / 4, 256>>>(en, out);
}

// round 8
// speedup vs baseline: 1.1183x; 1.1183x over previous
#include <cuda_runtime.h>
#include <cuda_bf16.h>
#include <cstdint>

#define BB 4
#define HH 256
#define CC 80
#define TX 256
#define TY 1024
#define NEGV (-1e9f)

// Output layout (float32):
#define OFF_OEN  0
#define OFF_LOGP 1048576
#define OFF_ATTN 2097152
#define OFF_DR   3145728

// -------- device scratch --------
__device__ float g_A  [BB*CC*TX];
__device__ float g_Bc [BB*CC*TX];
__device__ float g_cst[BB*TX];
__device__ float g_lpT[BB*TY*TX];   // masked logp, transposed [b][y][x]
__device__ int   g_idx[BB*TY];      // alignment index per y (-1 = inactive)

__device__ __forceinline__ void cp_async16(void* smem_dst, const void* gmem_src) {
    unsigned sa = (unsigned)__cvta_generic_to_shared(smem_dst);
    asm volatile("cp.async.cg.shared.global [%0], [%1], 16;\n"
                 :: "r"(sa), "l"(gmem_src));
}

// =====================================================================
// K0: slot-shift no-op so ncu's captured slot (4th launch) lands on k_dp
// =====================================================================
__global__ void k_slot() {}

// =====================================================================
// K1: per-(b,x) channel precompute
// =====================================================================
__global__ void k_pre(const float* __restrict__ mu,
                      const float* __restrict__ ls) {
    int b = blockIdx.x;
    int x = threadIdx.x;
    float s3 = 0.f, sl = 0.f;
    #pragma unroll 4
    for (int c = 0; c < CC; c++) {
        int o = (b * CC + c) * TX + x;
        float l = ls[o];
        float m = mu[o];
        float w = expf(-2.0f * l);
        g_A [o] = (-0.5f / (float)CC) * w;
        g_Bc[o] = (1.0f / (float)CC) * w * m;
        s3 += w * m * m;
        sl += l;
    }
    g_cst[b * TX + x] = (-0.5f / (float)CC) * (s3 + sl);
}

// =====================================================================
// K2: logp GEMM  logp[b,x,y] = sum_c A*y^2 + B*y + cst
// =====================================================================
#define TSX 64
#define TSY 64
#define KCH 40

__global__ __launch_bounds__(256, 2)
void k_logp(const float* __restrict__ y,
            const int* __restrict__ xl,
            const int* __restrict__ yl,
            float* __restrict__ out) {
    __shared__ float sA [KCH][TSX];
    __shared__ float sB [KCH][TSX];
    __shared__ float sY [KCH][TSY];
    __shared__ float sY2[KCH][TSY];

    int b  = blockIdx.z;
    int x0 = blockIdx.y * TSX;
    int y0 = blockIdx.x * TSY;
    int tid = threadIdx.x;
    int ty = tid & 15;
    int tx = tid >> 4;
    int xr = tx * 4;
    int yc = ty * 4;

    float acc[4][4] = {};

    for (int kc = 0; kc < CC; kc += KCH) {
        __syncthreads();
        #pragma unroll
        for (int i = tid; i < KCH * TSX; i += 256) {
            int c = i >> 6, j = i & 63;
            int oa = (b * CC + (kc + c)) * TX + x0 + j;
            sA[c][j] = g_A[oa];
            sB[c][j] = g_Bc[oa];
            float yv = y[(b * CC + (kc + c)) * TY + y0 + j];
            sY [c][j] = yv;
            sY2[c][j] = yv * yv;
        }
        __syncthreads();

        #pragma unroll 8
        for (int c = 0; c < KCH; c++) {
            float4 a  = *(const float4*)&sA [c][xr];
            float4 bb = *(const float4*)&sB [c][xr];
            float4 yv = *(const float4*)&sY [c][yc];
            float4 y2 = *(const float4*)&sY2[c][yc];
            float av[4] = {a.x, a.y, a.z, a.w};
            float bv[4] = {bb.x, bb.y, bb.z, bb.w};
            float yvv[4] = {yv.x, yv.y, yv.z, yv.w};
            float y2v[4] = {y2.x, y2.y, y2.z, y2.w};
            #pragma unroll
            for (int i = 0; i < 4; i++)
                #pragma unroll
                for (int j = 0; j < 4; j++) {
                    acc[i][j] = fmaf(av[i], y2v[j], acc[i][j]);
                    acc[i][j] = fmaf(bv[i], yvv[j], acc[i][j]);
                }
        }
    }

    float cst_i[4];
    #pragma unroll
    for (int i = 0; i < 4; i++)
        cst_i[i] = g_cst[b * TX + x0 + xr + i];

    int xlen = xl[b], ylen = yl[b];

    #pragma unroll
    for (int i = 0; i < 4; i++) {
        int gx = x0 + xr + i;
        float4 r;
        r.x = acc[i][0] + cst_i[i];
        r.y = acc[i][1] + cst_i[i];
        r.z = acc[i][2] + cst_i[i];
        r.w = acc[i][3] + cst_i[i];
        *(float4*)&out[OFF_LOGP + ((size_t)(b * TX + gx)) * TY + y0 + yc] = r;
    }

    #pragma unroll
    for (int j = 0; j < 4; j++) {
        int gy = y0 + yc + j;
        bool ym = gy < ylen;
        float4 t;
        t.x = (ym && (x0 + xr + 0) < xlen) ? acc[0][j] + cst_i[0] : NEGV;
        t.y = (ym && (x0 + xr + 1) < xlen) ? acc[1][j] + cst_i[1] : NEGV;
        t.z = (ym && (x0 + xr + 2) < xlen) ? acc[2][j] + cst_i[2] : NEGV;
        t.w = (ym && (x0 + xr + 3) < xlen) ? acc[3][j] + cst_i[3] : NEGV;
        *(float4*)&g_lpT[((size_t)(b * TY + gy)) * TX + x0 + xr] = t;
    }
}

// =====================================================================
// K3: Viterbi DP — x-split warp cascade, 1 __syncthreads per 32-row phase.
//   w0: recurrence x[0,128),   chunk p   (4 x/lane, 1 LDS + 1 STS per step)
//   w1: recurrence x[128,256), chunk p-1 (edge from w0 via smem)
//   w2: cp.async producer chunk p+1 + diag bits x[0,128) for chunk p-2
//   w3: diag bits x[128,256) for chunk p-2
// =====================================================================
#define DPC 32
// smem layout (bytes):
//   rows:  float4[3][32*64]  = 98304   @ 0
//   vring: float4[3][32*64]  = 98304   @ 98304
//   diag:  unsigned[32][256] = 32768   @ 196608
//   edge:  float[3][32]      = 384     @ 229376
//   dr:    int[256]          = 1024    @ 229760
//   cum:   int[257]          = 1028    @ 230784
#define DP_SMEM_BYTES 231812

__global__ __launch_bounds__(128, 1)
void k_dp(const int* __restrict__ xl,
          const int* __restrict__ yl,
          float* __restrict__ out) {
    extern __shared__ char smem[];
    float4*   rows  = (float4*)smem;                      // [3][2048]
    float4*   vring = (float4*)(smem + 98304);            // [3][2048]
    unsigned* diag  = (unsigned*)(smem + 196608);         // [32][256]
    float*    edge  = (float*)(smem + 229376);            // [3][32]
    int*      s_dr  = (int*)(smem + 229760);
    int*      s_cum = (int*)(smem + 230784);

    int b    = blockIdx.x;
    int tid  = threadIdx.x;
    int wid  = tid >> 5;
    int lane = tid & 31;

    int xlen = xl[b], ylen = yl[b];
    int nck  = (ylen + DPC - 1) / DPC;     // 16..32 chunks of 32 rows

    const float4* lp4 = (const float4*)(g_lpT + (size_t)b * TY * TX);

    s_dr[tid] = 0; s_dr[tid + 128] = 0;
    if (tid == 0) edge[2 * 32 + 31] = NEGV;   // v_init[127] for w1's chunk 0

    // prologue: all warps cp.async chunk 0 into rows[0]
    for (int i = tid; i < 2048; i += 128)
        cp_async16(rows + i, lp4 + i);
    asm volatile("cp.async.commit_group;\n");
    asm volatile("cp.async.wait_group 0;\n" ::: "memory");
    __syncthreads();

    if (wid == 0) {
        // -------- w0: recurrence x in [0,128) --------
        float4 v = make_float4(NEGV, NEGV, NEGV, NEGV);
        if (lane == 0) v.x = 0.0f;
        bool l0 = (lane == 0), l31 = (lane == 31);

        #pragma unroll 1
        for (int p = 0; p < nck + 2; p++) {
            if (p < nck) {
                const float4* rb = rows  + (p % 3) * 2048;
                float4*       vr = vring + (p % 3) * 2048;
                float*        eC = edge + (p % 3) * 32;
                float4 c_cur = rb[lane];
                float4 c_nxt = rb[64 + lane];
                #pragma unroll
                for (int r = 0; r < 32; r++) {
                    float4 c_n2 = rb[((r < 30) ? (r + 2) * 64 : 0) + lane];
                    float top = __shfl_up_sync(0xffffffffu, v.w, 1);
                    if (l0) top = NEGV;
                    float4 nv;
                    nv.x = c_cur.x + fmaxf(v.x, top);
                    nv.y = c_cur.y + fmaxf(v.y, v.x);
                    nv.z = c_cur.z + fmaxf(v.z, v.y);
                    nv.w = c_cur.w + fmaxf(v.w, v.z);
                    v = nv;
                    vr[r * 64 + lane] = v;
                    if (l31) eC[r] = v.w;
                    c_cur = c_nxt; c_nxt = c_n2;
                }
            }
            __syncthreads();
        }
    } else if (wid == 1) {
        // -------- w1: recurrence x in [128,256), one phase behind --------
        float4 v = make_float4(NEGV, NEGV, NEGV, NEGV);
        bool l0 = (lane == 0);
        float carry_e = NEGV;   // v[127] at end of previous chunk

        #pragma unroll 1
        for (int p = 0; p < nck + 2; p++) {
            int ck = p - 1;
            if (ck >= 0 && ck < nck) {
                const float4* rb = rows  + (ck % 3) * 2048;
                float4*       vr = vring + (ck % 3) * 2048;
                const float*  eC = edge + (ck % 3) * 32;
                if (ck == 0) carry_e = edge[2 * 32 + 31];
                float4 c_cur = rb[32 + lane];
                float4 c_nxt = rb[96 + lane];
                float e_nxt = eC[0];           // edge for row 1
                #pragma unroll
                for (int r = 0; r < 32; r++) {
                    float4 c_n2 = rb[((r < 30) ? (r + 2) * 64 : 0) + 32 + lane];
                    float e_cur = (r == 0) ? carry_e : e_nxt;
                    float e_n2  = eC[(r < 31) ? r : 31];
                    float top = __shfl_up_sync(0xffffffffu, v.w, 1);
                    if (l0) top = e_cur;
                    float4 nv;
                    nv.x = c_cur.x + fmaxf(v.x, top);
                    nv.y = c_cur.y + fmaxf(v.y, v.x);
                    nv.z = c_cur.z + fmaxf(v.z, v.y);
                    nv.w = c_cur.w + fmaxf(v.w, v.z);
                    v = nv;
                    vr[r * 64 + 32 + lane] = v;
                    c_cur = c_nxt; c_nxt = c_n2;
                    if (r > 0) e_nxt = e_n2;
                }
                carry_e = eC[31];
            }
            __syncthreads();
        }
    } else if (wid == 2) {
        // -------- w2: producer (chunk p+1) + diag bits x[0,128) (chunk p-2) --
        float4 P = make_float4(NEGV, NEGV, NEGV, NEGV);   // v_init low
        if (lane == 0) P.x = 0.0f;
        bool l0 = (lane == 0);

        #pragma unroll 1
        for (int p = 0; p < nck + 2; p++) {
            if (p + 1 < nck) {
                const float4* src = lp4 + (p + 1) * 2048;
                float4* dst = rows + ((p + 1) % 3) * 2048;
                #pragma unroll
                for (int i = 0; i < 64; i++)
                    cp_async16(dst + i * 32 + lane, src + i * 32 + lane);
                asm volatile("cp.async.commit_group;\n");
            }
            int ck = p - 2;
            if (ck >= 0) {
                const float4* vr = vring + (ck % 3) * 2048;
                unsigned db0 = 0, db1 = 0, db2 = 0, db3 = 0;
                #pragma unroll
                for (int r = 0; r < 32; r++) {
                    float4 C = vr[r * 64 + lane];
                    float pm1 = __shfl_up_sync(0xffffffffu, P.w, 1);
                    if (l0) pm1 = NEGV;
                    unsigned bit = 1u << r;
                    if (pm1 > P.x) db0 |= bit;
                    if (P.x > P.y) db1 |= bit;
                    if (P.y > P.z) db2 |= bit;
                    if (P.z > P.w) db3 |= bit;
                    P = C;
                }
                *(uint4*)&diag[ck * 256 + lane * 4] =
                    make_uint4(db0, db1, db2, db3);
            }
            if (p + 1 < nck)
                asm volatile("cp.async.wait_group 0;\n" ::: "memory");
            __syncthreads();
        }
    } else {
        // -------- w3: diag bits x[128,256) (chunk p-2) --------
        float4 P = make_float4(NEGV, NEGV, NEGV, NEGV);   // v_init high
        float s127 = NEGV;                                 // v[127] @ row-1
        bool l0 = (lane == 0);

        #pragma unroll 1
        for (int p = 0; p < nck + 2; p++) {
            int ck = p - 2;
            if (ck >= 0) {
                const float4* vr = vring + (ck % 3) * 2048;
                unsigned db0 = 0, db1 = 0, db2 = 0, db3 = 0;
                #pragma unroll
                for (int r = 0; r < 32; r++) {
                    float4 C = vr[r * 64 + 32 + lane];
                    float pm1 = __shfl_up_sync(0xffffffffu, P.w, 1);
                    if (l0) pm1 = s127;
                    unsigned bit = 1u << r;
                    if (pm1 > P.x) db0 |= bit;
                    if (P.x > P.y) db1 |= bit;
                    if (P.y > P.z) db2 |= bit;
                    if (P.z > P.w) db3 |= bit;
                    P = C;
                    if (l0) s127 = ((const float*)(vr + r * 64))[127];
                }
                *(uint4*)&diag[ck * 256 + 128 + lane * 4] =
                    make_uint4(db0, db1, db2, db3);
            }
            __syncthreads();
        }
    }
    __syncthreads();

    // ---- backtrack: run-length over diag words (lane 0) ----
    if (tid == 0) {
        int idx = xlen - 1;
        int yy  = ylen - 1;
        while (yy >= 0) {
            if (idx == 0) { s_dr[0] += yy + 1; break; }
            int yw = yy >> 5;
            unsigned mask = ((yy & 31) == 31) ? 0xffffffffu
                                              : ((2u << (yy & 31)) - 1u);
            unsigned m = diag[yw * 256 + idx] & mask;
            if (m) {
                int ystar = (yw << 5) + (31 - __clz(m));
                s_dr[idx] += yy - ystar + 1;
                idx--;
                yy = ystar - 1;
            } else {
                s_dr[idx] += yy - (yw << 5) + 1;
                yy = (yw << 5) - 1;
            }
        }
    }
    __syncthreads();

    // ---- exclusive cumsum of durations (warp 0) ----
    if (wid == 0) {
        int t[8], run[8];
        int tot = 0;
        #pragma unroll
        for (int i = 0; i < 8; i++) {
            t[i] = s_dr[lane * 8 + i];
            tot += t[i];
            run[i] = tot;
        }
        int sc = tot;
        #pragma unroll
        for (int d = 1; d < 32; d <<= 1) {
            int n = __shfl_up_sync(0xffffffffu, sc, d);
            if (lane >= d) sc += n;
        }
        int excl = sc - tot;
        if (lane == 0) s_cum[0] = 0;
        #pragma unroll
        for (int i = 0; i < 8; i++)
            s_cum[lane * 8 + i + 1] = excl + run[i];

        #pragma unroll
        for (int i = 0; i < 8; i++)
            out[OFF_DR + b * TX + lane * 8 + i] = (float)t[i];
    }
    __syncthreads();

    // ---- g_idx via binary search (8 y per thread) ----
    #pragma unroll
    for (int k = 0; k < TY / 128; k++) {
        int yy = k * 128 + tid;
        int r = -1;
        if (yy < ylen) {
            int lo = 0, hi = TX - 1;
            #pragma unroll
            for (int s = 0; s < 8; s++) {
                int mid = (lo + hi) >> 1;
                if (yy >= s_cum[mid + 1]) lo = mid + 1; else hi = mid;
            }
            r = lo;
        }
        g_idx[b * TY + yy] = r;
    }
}

// =====================================================================
// K4: fused epilogue — 4 rows per block
// =====================================================================
__global__ __launch_bounds__(256)
void k_epi(const float* __restrict__ en, float* __restrict__ out) {
    __shared__ float se[4][TX];
    int bid = blockIdx.x;
    int tid = threadIdx.x;
    int row0 = bid * 4;

    if (row0 < BB * TX) {
        int b = row0 >> 8;
        int4 id = *(const int4*)&g_idx[b * TY + tid * 4];
        #pragma unroll
        for (int rr = 0; rr < 4; rr++) {
            int x = (row0 + rr) & 255;
            float4 r;
            r.x = (id.x == x) ? 1.0f : 0.0f;
            r.y = (id.y == x) ? 1.0f : 0.0f;
            r.z = (id.z == x) ? 1.0f : 0.0f;
            r.w = (id.w == x) ? 1.0f : 0.0f;
            *(float4*)&out[OFF_ATTN + (size_t)(row0 + rr) * TY + tid * 4] = r;
        }
    } else {
        int r0 = row0 - BB * TX;
        int b  = r0 >> 8;
        {
            int rr = tid >> 6;
            int h  = (r0 + rr) & 255;
            *(float4*)&se[rr][(tid & 63) * 4] =
                *(const float4*)&en[(b * HH + h) * TX + (tid & 63) * 4];
        }
        __syncthreads();
        int4 id = *(const int4*)&g_idx[b * TY + tid * 4];
        #pragma unroll
        for (int rr = 0; rr < 4; rr++) {
            float4 r;
            r.x = (id.x >= 0) ? se[rr][id.x] : 0.0f;
            r.y = (id.y >= 0) ? se[rr][id.y] : 0.0f;
            r.z = (id.z >= 0) ? se[rr][id.z] : 0.0f;
            r.w = (id.w >= 0) ? se[rr][id.w] : 0.0f;
            *(float4*)&out[OFF_OEN + (size_t)(r0 + rr) * TY + tid * 4] = r;
        }
    }
}

// =====================================================================
extern "C" void kernel_launch(void* const* d_in, const int* in_sizes, int n_in,
                              void* d_out, int out_size) {
    const float* en = (const float*)d_in[0];
    const float* mu = (const float*)d_in[1];
    const float* ls = (const float*)d_in[2];
    const float* y  = (const float*)d_in[3];
    const int*   xl = (const int*)d_in[4];
    const int*   yl = (const int*)d_in[5];
    float* out = (float*)d_out;

    cudaFuncSetAttribute(k_dp, cudaFuncAttributeMaxDynamicSharedMemorySize,
                         DP_SMEM_BYTES);

    k_pre<<<BB, TX>>>(mu, ls);

    dim3 g2(TY / TSY, TX / TSX, BB);   // (16, 4, 4)
    k_logp<<<g2, 256>>>(y, xl, yl, out);

    k_slot<<<1, 32>>>();               // keep ncu capture slot on k_dp

    k_dp<<<BB, 128, DP_SMEM_BYTES>>>(xl, yl, out);

    k_epi<<<2 * BB * TX / 4, 256>>>(en, out);
}